// round 3
// baseline (speedup 1.0000x reference)
#include <cuda_runtime.h>

#define N_NODES 100000
#define N_EDGES 800000
#define ANNOT 92
#define HID 64
#define N_STEPS 8
#define N_IDX 20000

typedef unsigned long long u64;

// ---- scratch (no allocations allowed) ----
__device__ float g_h[N_NODES * HID];
__device__ float g_m[N_NODES * HID];
__device__ float g_aggr[N_NODES * HID];

// ---- packed f32x2 helpers (sm_103a FFMA2 path, PTX-only) ----
__device__ __forceinline__ u64 ffma2(u64 a, u64 b, u64 c) {
    u64 d;
    asm("fma.rn.f32x2 %0, %1, %2, %3;" : "=l"(d) : "l"(a), "l"(b), "l"(c));
    return d;
}
__device__ __forceinline__ u64 dup2(float v) {
    unsigned u = __float_as_uint(v);
    u64 d;
    asm("mov.b64 %0, {%1, %2};" : "=l"(d) : "r"(u), "r"(u));
    return d;
}
__device__ __forceinline__ float lo2(u64 v) { return __uint_as_float((unsigned)v); }
__device__ __forceinline__ float hi2(u64 v) { return __uint_as_float((unsigned)(v >> 32)); }

__device__ __forceinline__ float sigm(float x) { return 1.f / (1.f + __expf(-x)); }
__device__ __forceinline__ float tanh_f(float x) { return 1.f - 2.f / (__expf(2.f * x) + 1.f); }

// =====================================================================
// reduce: h = x @ W_red + b_red        [100000,92] @ [92,64]
// =====================================================================
#define RNW 16
#define RNT 2
__global__ __launch_bounds__(512) void reduce_kernel(
    const float* __restrict__ x, const float* __restrict__ W,
    const float* __restrict__ b, float* __restrict__ h) {
    extern __shared__ char smraw[];
    float* s_w = (float*)smraw;                 // [92][64], already [k][j]
    u64* s_x = (u64*)(s_w + ANNOT * HID);       // RNW*RNT*92 duplicated pairs
    int tid = threadIdx.x, lane = tid & 31, warp = tid >> 5;
    for (int i = tid; i < ANNOT * HID; i += blockDim.x) s_w[i] = W[i];
    __syncthreads();
    u64* my_x = s_x + warp * (RNT * ANNOT);
    int j0 = lane * 2;
    u64 bias = *(const u64*)(b + j0);
    int stride = gridDim.x * RNW * RNT;
    for (int base = (blockIdx.x * RNW + warp) * RNT; base < N_NODES; base += stride) {
        for (int t = 0; t < RNT; t++) {
            int node = base + t; if (node >= N_NODES) node = N_NODES - 1;
            const float* xr = x + (size_t)node * ANNOT;
            my_x[t * ANNOT + lane]      = dup2(xr[lane]);
            my_x[t * ANNOT + 32 + lane] = dup2(xr[32 + lane]);
            if (lane < ANNOT - 64) my_x[t * ANNOT + 64 + lane] = dup2(xr[64 + lane]);
        }
        __syncwarp();
        u64 acc[RNT];
        #pragma unroll
        for (int t = 0; t < RNT; t++) acc[t] = bias;
        #pragma unroll 4
        for (int k = 0; k < ANNOT; k++) {
            u64 w = *(const u64*)(s_w + k * HID + j0);
            #pragma unroll
            for (int t = 0; t < RNT; t++) acc[t] = ffma2(my_x[t * ANNOT + k], w, acc[t]);
        }
        #pragma unroll
        for (int t = 0; t < RNT; t++) {
            int node = base + t;
            if (node < N_NODES)
                *(float2*)(h + (size_t)node * HID + j0) = make_float2(lo2(acc[t]), hi2(acc[t]));
        }
        __syncwarp();
    }
}

// =====================================================================
// transform: m = h @ W_g[t], and zero aggr (fused, same footprint)
// =====================================================================
#define TNW 16
#define TNT 4
__global__ __launch_bounds__(512) void transform_kernel(
    const float* __restrict__ h, const float* __restrict__ Wg,
    float* __restrict__ m, float* __restrict__ aggr) {
    extern __shared__ char smraw[];
    float* s_w = (float*)smraw;                 // [64][64] = W_g[k][j]
    u64* s_h = (u64*)(s_w + HID * HID);
    int tid = threadIdx.x, lane = tid & 31, warp = tid >> 5;
    for (int i = tid; i < HID * HID; i += blockDim.x) s_w[i] = Wg[i];
    __syncthreads();
    u64* my_h = s_h + warp * (TNT * HID);
    int j0 = lane * 2;
    int stride = gridDim.x * TNW * TNT;
    for (int base = (blockIdx.x * TNW + warp) * TNT; base < N_NODES; base += stride) {
        for (int t = 0; t < TNT; t++) {
            int node = base + t; if (node >= N_NODES) node = N_NODES - 1;
            const float* hr = h + (size_t)node * HID;
            my_h[t * HID + lane]      = dup2(hr[lane]);
            my_h[t * HID + 32 + lane] = dup2(hr[32 + lane]);
        }
        __syncwarp();
        u64 acc[TNT] = {0ull, 0ull, 0ull, 0ull};
        #pragma unroll 4
        for (int k = 0; k < HID; k++) {
            u64 w = *(const u64*)(s_w + k * HID + j0);
            #pragma unroll
            for (int t = 0; t < TNT; t++) acc[t] = ffma2(my_h[t * HID + k], w, acc[t]);
        }
        #pragma unroll
        for (int t = 0; t < TNT; t++) {
            int node = base + t;
            if (node < N_NODES) {
                *(float2*)(m    + (size_t)node * HID + j0) = make_float2(lo2(acc[t]), hi2(acc[t]));
                *(float2*)(aggr + (size_t)node * HID + j0) = make_float2(0.f, 0.f);
            }
        }
        __syncwarp();
    }
}

// =====================================================================
// scatter: aggr[dst] += m[src] over 800k edges. 16 threads/edge, float4
// vector atomics (sm_90+) -> 1 RED.128 per thread.
// NOTE: edge_index arrives as int32 (JAX x64 disabled downgrades int64).
// =====================================================================
__global__ __launch_bounds__(256) void scatter_kernel(
    const float* __restrict__ m, const int* __restrict__ ei,
    float* __restrict__ aggr) {
    unsigned tid = blockIdx.x * blockDim.x + threadIdx.x;
    unsigned e = tid >> 4, p = tid & 15;
    if (e >= N_EDGES) return;
    int s = ei[e];
    int d = ei[N_EDGES + e];
    float4 v = ((const float4*)(m + (size_t)s * HID))[p];
    atomicAdd((float4*)(aggr + (size_t)d * HID + p * 4), v);
}

// =====================================================================
// GRU cell: h = GRUCell(aggr, h). Weights transposed into smem [k][j],
// 8 nodes register-tiled per thread, all dots as FFMA2.
// =====================================================================
#define GNW 8
#define GNT 8
__global__ __launch_bounds__(256) void gru_kernel(
    const float* __restrict__ aggr, float* __restrict__ h,
    const float* __restrict__ w_ih, const float* __restrict__ w_hh,
    const float* __restrict__ b_ih, const float* __restrict__ b_hh) {
    extern __shared__ char smraw[];
    float* s_wi = (float*)smraw;                  // [64][192]
    float* s_wh = s_wi + HID * 192;               // [64][192]
    u64* s_a = (u64*)(s_wh + HID * 192);          // GNW*GNT*64 dup pairs
    u64* s_hs = s_a + GNW * GNT * HID;
    int tid = threadIdx.x, lane = tid & 31, warp = tid >> 5;
    for (int i = tid; i < 192 * HID; i += blockDim.x) {
        int j = i >> 6, k = i & 63;               // w[j][k] row-major
        s_wi[k * 192 + j] = w_ih[i];
        s_wh[k * 192 + j] = w_hh[i];
    }
    __syncthreads();
    u64* my_a = s_a + warp * (GNT * HID);
    u64* my_h = s_hs + warp * (GNT * HID);
    int j0 = lane * 2;
    u64 bir = *(const u64*)(b_ih + j0), biz = *(const u64*)(b_ih + 64 + j0), bin_ = *(const u64*)(b_ih + 128 + j0);
    u64 bhr = *(const u64*)(b_hh + j0), bhz = *(const u64*)(b_hh + 64 + j0), bhn = *(const u64*)(b_hh + 128 + j0);
    int stride = gridDim.x * GNW * GNT;
    for (int base = (blockIdx.x * GNW + warp) * GNT; base < N_NODES; base += stride) {
        for (int t = 0; t < GNT; t++) {
            int node = base + t; if (node >= N_NODES) node = N_NODES - 1;
            const float* ar = aggr + (size_t)node * HID;
            const float* hr = h + (size_t)node * HID;
            my_a[t * HID + lane]      = dup2(ar[lane]);
            my_a[t * HID + 32 + lane] = dup2(ar[32 + lane]);
            my_h[t * HID + lane]      = dup2(hr[lane]);
            my_h[t * HID + 32 + lane] = dup2(hr[32 + lane]);
        }
        __syncwarp();
        u64 ir[GNT], iz[GNT], in_[GNT], hr_[GNT], hz[GNT], hn[GNT];
        #pragma unroll
        for (int t = 0; t < GNT; t++) {
            ir[t] = bir; iz[t] = biz; in_[t] = bin_;
            hr_[t] = bhr; hz[t] = bhz; hn[t] = bhn;
        }
        #pragma unroll 2
        for (int k = 0; k < HID; k++) {
            u64 wr = *(const u64*)(s_wi + k * 192 + j0);
            u64 wz = *(const u64*)(s_wi + k * 192 + 64 + j0);
            u64 wn = *(const u64*)(s_wi + k * 192 + 128 + j0);
            u64 vr = *(const u64*)(s_wh + k * 192 + j0);
            u64 vz = *(const u64*)(s_wh + k * 192 + 64 + j0);
            u64 vn = *(const u64*)(s_wh + k * 192 + 128 + j0);
            #pragma unroll
            for (int t = 0; t < GNT; t++) {
                u64 a = my_a[t * HID + k];
                u64 hh = my_h[t * HID + k];
                ir[t]  = ffma2(a, wr, ir[t]);
                iz[t]  = ffma2(a, wz, iz[t]);
                in_[t] = ffma2(a, wn, in_[t]);
                hr_[t] = ffma2(hh, vr, hr_[t]);
                hz[t]  = ffma2(hh, vz, hz[t]);
                hn[t]  = ffma2(hh, vn, hn[t]);
            }
        }
        #pragma unroll
        for (int t = 0; t < GNT; t++) {
            int node = base + t;
            if (node < N_NODES) {
                float hv0 = lo2(my_h[t * HID + j0]);
                float hv1 = lo2(my_h[t * HID + j0 + 1]);
                float r0 = sigm(lo2(ir[t]) + lo2(hr_[t]));
                float r1 = sigm(hi2(ir[t]) + hi2(hr_[t]));
                float z0 = sigm(lo2(iz[t]) + lo2(hz[t]));
                float z1 = sigm(hi2(iz[t]) + hi2(hz[t]));
                float n0 = tanh_f(lo2(in_[t]) + r0 * lo2(hn[t]));
                float n1 = tanh_f(hi2(in_[t]) + r1 * hi2(hn[t]));
                float o0 = (1.f - z0) * n0 + z0 * hv0;
                float o1 = (1.f - z1) * n1 + z1 * hv1;
                *(float2*)(h + (size_t)node * HID + j0) = make_float2(o0, o1);
            }
        }
        __syncwarp();
    }
}

// =====================================================================
// select + head: out[b] = sigmoid(h[idx[b]] . W_lin + b_lin)
// =====================================================================
__global__ __launch_bounds__(256) void select_kernel(
    const float* __restrict__ h, const int* __restrict__ idx,
    const float* __restrict__ W, const float* __restrict__ bl,
    float* __restrict__ out) {
    int g = blockIdx.x * blockDim.x + threadIdx.x;
    int w = g >> 5, lane = g & 31;
    if (w >= N_IDX) return;
    int node = idx[w];
    const float* hr = h + (size_t)node * HID;
    float s = hr[lane] * W[lane] + hr[32 + lane] * W[32 + lane];
    #pragma unroll
    for (int o = 16; o; o >>= 1) s += __shfl_xor_sync(0xffffffffu, s, o);
    if (lane == 0) out[w] = sigm(s + bl[0]);
}

// =====================================================================
extern "C" void kernel_launch(void* const* d_in, const int* in_sizes, int n_in,
                              void* d_out, int out_size) {
    const float* x        = (const float*)d_in[0];
    const int*   ei       = (const int*)d_in[1];    // int32 (JAX default x64 off)
    const int*   idx      = (const int*)d_in[2];    // int32
    const float* W_red    = (const float*)d_in[3];
    const float* b_red    = (const float*)d_in[4];
    const float* W_g      = (const float*)d_in[5];
    const float* w_ih     = (const float*)d_in[6];
    const float* w_hh     = (const float*)d_in[7];
    const float* b_ih     = (const float*)d_in[8];
    const float* b_hh     = (const float*)d_in[9];
    const float* W_lin    = (const float*)d_in[10];
    const float* b_lin    = (const float*)d_in[11];
    float* out = (float*)d_out;

    void *ph, *pm, *pa;
    cudaGetSymbolAddress(&ph, g_h);
    cudaGetSymbolAddress(&pm, g_m);
    cudaGetSymbolAddress(&pa, g_aggr);
    float* h_p = (float*)ph;
    float* m_p = (float*)pm;
    float* a_p = (float*)pa;

    const int RED_SMEM = ANNOT * HID * 4 + RNW * RNT * ANNOT * 8;            // ~47 KB
    const int TR_SMEM  = HID * HID * 4 + TNW * TNT * HID * 8;                // 48 KB
    const int GRU_SMEM = 2 * 192 * HID * 4 + 2 * GNW * GNT * HID * 8;        // 160 KB
    cudaFuncSetAttribute(reduce_kernel,    cudaFuncAttributeMaxDynamicSharedMemorySize, RED_SMEM);
    cudaFuncSetAttribute(transform_kernel, cudaFuncAttributeMaxDynamicSharedMemorySize, TR_SMEM);
    cudaFuncSetAttribute(gru_kernel,       cudaFuncAttributeMaxDynamicSharedMemorySize, GRU_SMEM);

    reduce_kernel<<<592, 512, RED_SMEM>>>(x, W_red, b_red, h_p);
    for (int t = 0; t < N_STEPS; t++) {
        transform_kernel<<<592, 512, TR_SMEM>>>(h_p, W_g + (size_t)t * HID * HID, m_p, a_p);
        scatter_kernel<<<(N_EDGES * 16) / 256, 256>>>(m_p, ei, a_p);
        gru_kernel<<<148, 256, GRU_SMEM>>>(a_p, h_p, w_ih, w_hh, b_ih, b_hh);
    }
    select_kernel<<<(N_IDX * 32 + 255) / 256, 256>>>(h_p, idx, W_lin, b_lin, out);
}

// round 6
// speedup vs baseline: 1.3557x; 1.3557x over previous
#include <cuda_runtime.h>

#define N_NODES 100000
#define N_EDGES 800000
#define ANNOT 92
#define HID 64
#define N_STEPS 8
#define N_IDX 20000

typedef unsigned long long u64;

// ---- scratch (no allocations allowed) ----
__device__ float g_h[N_NODES * HID];
__device__ float g_m[N_NODES * HID];
__device__ float g_aggr[N_NODES * HID];

// ---- packed f32x2 helpers (sm_103a FFMA2 path, PTX-only) ----
__device__ __forceinline__ u64 ffma2(u64 a, u64 b, u64 c) {
    u64 d;
    asm("fma.rn.f32x2 %0, %1, %2, %3;" : "=l"(d) : "l"(a), "l"(b), "l"(c));
    return d;
}
__device__ __forceinline__ u64 dup2(float v) {
    unsigned u = __float_as_uint(v);
    u64 d;
    asm("mov.b64 %0, {%1, %2};" : "=l"(d) : "r"(u), "r"(u));
    return d;
}
__device__ __forceinline__ float lo2(u64 v) { return __uint_as_float((unsigned)v); }
__device__ __forceinline__ float hi2(u64 v) { return __uint_as_float((unsigned)(v >> 32)); }

__device__ __forceinline__ float sigm(float x) { return 1.f / (1.f + __expf(-x)); }
__device__ __forceinline__ float tanh_f(float x) { return 1.f - 2.f / (__expf(2.f * x) + 1.f); }

// =====================================================================
// reduce: h = x @ W_red + b_red        [100000,92] @ [92,64]
// =====================================================================
#define RNW 16
#define RNT 2
__global__ __launch_bounds__(512) void reduce_kernel(
    const float* __restrict__ x, const float* __restrict__ W,
    const float* __restrict__ b, float* __restrict__ h) {
    extern __shared__ char smraw[];
    float* s_w = (float*)smraw;                 // [92][64], already [k][j]
    u64* s_x = (u64*)(s_w + ANNOT * HID);       // RNW*RNT*92 duplicated pairs
    int tid = threadIdx.x, lane = tid & 31, warp = tid >> 5;
    for (int i = tid; i < ANNOT * HID; i += blockDim.x) s_w[i] = W[i];
    __syncthreads();
    u64* my_x = s_x + warp * (RNT * ANNOT);
    int j0 = lane * 2;
    u64 bias = *(const u64*)(b + j0);
    int stride = gridDim.x * RNW * RNT;
    for (int base = (blockIdx.x * RNW + warp) * RNT; base < N_NODES; base += stride) {
        for (int t = 0; t < RNT; t++) {
            int node = base + t; if (node >= N_NODES) node = N_NODES - 1;
            const float* xr = x + (size_t)node * ANNOT;
            my_x[t * ANNOT + lane]      = dup2(xr[lane]);
            my_x[t * ANNOT + 32 + lane] = dup2(xr[32 + lane]);
            if (lane < ANNOT - 64) my_x[t * ANNOT + 64 + lane] = dup2(xr[64 + lane]);
        }
        __syncwarp();
        u64 acc[RNT];
        #pragma unroll
        for (int t = 0; t < RNT; t++) acc[t] = bias;
        #pragma unroll 4
        for (int k = 0; k < ANNOT; k++) {
            u64 w = *(const u64*)(s_w + k * HID + j0);
            #pragma unroll
            for (int t = 0; t < RNT; t++) acc[t] = ffma2(my_x[t * ANNOT + k], w, acc[t]);
        }
        #pragma unroll
        for (int t = 0; t < RNT; t++) {
            int node = base + t;
            if (node < N_NODES)
                *(float2*)(h + (size_t)node * HID + j0) = make_float2(lo2(acc[t]), hi2(acc[t]));
        }
        __syncwarp();
    }
}

// =====================================================================
// transform0: m = h @ W_g[0], zero aggr (only used for step 0)
// =====================================================================
#define TNW 16
#define TNT 4
__global__ __launch_bounds__(512) void transform_kernel(
    const float* __restrict__ h, const float* __restrict__ Wg,
    float* __restrict__ m, float* __restrict__ aggr) {
    extern __shared__ char smraw[];
    float* s_w = (float*)smraw;                 // [64][64] = W_g[k][j]
    u64* s_h = (u64*)(s_w + HID * HID);
    int tid = threadIdx.x, lane = tid & 31, warp = tid >> 5;
    for (int i = tid; i < HID * HID; i += blockDim.x) s_w[i] = Wg[i];
    __syncthreads();
    u64* my_h = s_h + warp * (TNT * HID);
    int j0 = lane * 2;
    int stride = gridDim.x * TNW * TNT;
    for (int base = (blockIdx.x * TNW + warp) * TNT; base < N_NODES; base += stride) {
        for (int t = 0; t < TNT; t++) {
            int node = base + t; if (node >= N_NODES) node = N_NODES - 1;
            const float* hr = h + (size_t)node * HID;
            my_h[t * HID + lane]      = dup2(hr[lane]);
            my_h[t * HID + 32 + lane] = dup2(hr[32 + lane]);
        }
        __syncwarp();
        u64 acc[TNT] = {0ull, 0ull, 0ull, 0ull};
        #pragma unroll 4
        for (int k = 0; k < HID; k++) {
            u64 w = *(const u64*)(s_w + k * HID + j0);
            #pragma unroll
            for (int t = 0; t < TNT; t++) acc[t] = ffma2(my_h[t * HID + k], w, acc[t]);
        }
        #pragma unroll
        for (int t = 0; t < TNT; t++) {
            int node = base + t;
            if (node < N_NODES) {
                *(float2*)(m    + (size_t)node * HID + j0) = make_float2(lo2(acc[t]), hi2(acc[t]));
                *(float2*)(aggr + (size_t)node * HID + j0) = make_float2(0.f, 0.f);
            }
        }
        __syncwarp();
    }
}

// =====================================================================
// scatter: aggr[dst] += m[src], 16 threads/edge, float4 vector atomics.
// edge_index arrives as int32 (JAX x64 disabled).
// =====================================================================
__global__ __launch_bounds__(256) void scatter_kernel(
    const float* __restrict__ m, const int* __restrict__ ei,
    float* __restrict__ aggr) {
    unsigned tid = blockIdx.x * blockDim.x + threadIdx.x;
    unsigned e = tid >> 4, p = tid & 15;
    if (e >= N_EDGES) return;
    int s = ei[e];
    int d = ei[N_EDGES + e];
    float4 v = ((const float4*)(m + (size_t)s * HID))[p];
    atomicAdd((float4*)(aggr + (size_t)d * HID + p * 4), v);
}

// =====================================================================
// Fused GRU + next-step transform:
//   h = GRUCell(aggr, h)
//   if (has_next): m = h @ Wg_next ; aggr = 0
// 384 threads (12 warps), 6 nodes/warp, non-duplicated f32 staging,
// register dup2 -> all dots as packed FFMA2.
// =====================================================================
#define GNW 12
#define GNT 6
__global__ __launch_bounds__(384) void gru_kernel(
    float* __restrict__ aggr, float* __restrict__ h, float* __restrict__ m,
    const float* __restrict__ w_ih, const float* __restrict__ w_hh,
    const float* __restrict__ b_ih, const float* __restrict__ b_hh,
    const float* __restrict__ Wg_next, int has_next) {
    extern __shared__ char smraw[];
    float* s_wi = (float*)smraw;                  // [64][192] transposed
    float* s_wh = s_wi + HID * 192;               // [64][192]
    float* s_wg = s_wh + HID * 192;               // [64][64]
    float* s_a  = s_wg + HID * HID;               // [GNW][GNT][64] plain f32
    float* s_hs = s_a + GNW * GNT * HID;          // [GNW][GNT][64]
    int tid = threadIdx.x, lane = tid & 31, warp = tid >> 5;
    for (int i = tid; i < 192 * HID; i += blockDim.x) {
        int j = i >> 6, k = i & 63;               // w[j][k] row-major
        s_wi[k * 192 + j] = w_ih[i];
        s_wh[k * 192 + j] = w_hh[i];
    }
    if (has_next)
        for (int i = tid; i < HID * HID; i += blockDim.x) s_wg[i] = Wg_next[i];
    __syncthreads();
    float* my_a = s_a  + warp * (GNT * HID);
    float* my_h = s_hs + warp * (GNT * HID);
    int j0 = lane * 2;
    u64 bir = *(const u64*)(b_ih + j0), biz = *(const u64*)(b_ih + 64 + j0), bin_ = *(const u64*)(b_ih + 128 + j0);
    u64 bhr = *(const u64*)(b_hh + j0), bhz = *(const u64*)(b_hh + 64 + j0), bhn = *(const u64*)(b_hh + 128 + j0);
    int stride = gridDim.x * GNW * GNT;
    for (int base = (blockIdx.x * GNW + warp) * GNT; base < N_NODES; base += stride) {
        // ---- stage activations (plain f32, coalesced) ----
        #pragma unroll
        for (int t = 0; t < GNT; t++) {
            int node = base + t; if (node >= N_NODES) node = N_NODES - 1;
            const float* ar = aggr + (size_t)node * HID;
            const float* hr = h + (size_t)node * HID;
            my_a[t * HID + lane]      = ar[lane];
            my_a[t * HID + 32 + lane] = ar[32 + lane];
            my_h[t * HID + lane]      = hr[lane];
            my_h[t * HID + 32 + lane] = hr[32 + lane];
        }
        __syncwarp();
        // ---- gates ----
        u64 ir[GNT], iz[GNT], in_[GNT], hr_[GNT], hz[GNT], hn[GNT];
        #pragma unroll
        for (int t = 0; t < GNT; t++) {
            ir[t] = bir; iz[t] = biz; in_[t] = bin_;
            hr_[t] = bhr; hz[t] = bhz; hn[t] = bhn;
        }
        #pragma unroll 2
        for (int k2 = 0; k2 < HID / 2; k2++) {
            float2 fa[GNT], fh[GNT];
            #pragma unroll
            for (int t = 0; t < GNT; t++) {
                fa[t] = *(const float2*)(my_a + t * HID + 2 * k2);
                fh[t] = *(const float2*)(my_h + t * HID + 2 * k2);
            }
            #pragma unroll
            for (int kk = 0; kk < 2; kk++) {
                int k = 2 * k2 + kk;
                const float* wi = s_wi + k * 192;
                const float* wh = s_wh + k * 192;
                u64 wr = *(const u64*)(wi + j0);
                u64 wz = *(const u64*)(wi + 64 + j0);
                u64 wn = *(const u64*)(wi + 128 + j0);
                u64 vr = *(const u64*)(wh + j0);
                u64 vz = *(const u64*)(wh + 64 + j0);
                u64 vn = *(const u64*)(wh + 128 + j0);
                #pragma unroll
                for (int t = 0; t < GNT; t++) {
                    u64 ad = dup2(kk ? fa[t].y : fa[t].x);
                    u64 hd = dup2(kk ? fh[t].y : fh[t].x);
                    ir[t]  = ffma2(ad, wr, ir[t]);
                    iz[t]  = ffma2(ad, wz, iz[t]);
                    in_[t] = ffma2(ad, wn, in_[t]);
                    hr_[t] = ffma2(hd, vr, hr_[t]);
                    hz[t]  = ffma2(hd, vz, hz[t]);
                    hn[t]  = ffma2(hd, vn, hn[t]);
                }
            }
        }
        // ---- GRU nonlinearity + h writeback + restage h_new ----
        #pragma unroll
        for (int t = 0; t < GNT; t++) {
            int node = base + t;
            float hv0 = my_h[t * HID + j0];
            float hv1 = my_h[t * HID + j0 + 1];
            float r0 = sigm(lo2(ir[t]) + lo2(hr_[t]));
            float r1 = sigm(hi2(ir[t]) + hi2(hr_[t]));
            float z0 = sigm(lo2(iz[t]) + lo2(hz[t]));
            float z1 = sigm(hi2(iz[t]) + hi2(hz[t]));
            float n0 = tanh_f(lo2(in_[t]) + r0 * lo2(hn[t]));
            float n1 = tanh_f(hi2(in_[t]) + r1 * hi2(hn[t]));
            float o0 = (1.f - z0) * n0 + z0 * hv0;
            float o1 = (1.f - z1) * n1 + z1 * hv1;
            if (node < N_NODES)
                *(float2*)(h + (size_t)node * HID + j0) = make_float2(o0, o1);
            *(float2*)(my_h + t * HID + j0) = make_float2(o0, o1);
        }
        __syncwarp();
        // ---- fused transform for next step: m = h_new @ Wg_next ----
        if (has_next) {
            u64 macc[GNT];
            #pragma unroll
            for (int t = 0; t < GNT; t++) macc[t] = 0ull;
            #pragma unroll 2
            for (int k2 = 0; k2 < HID / 2; k2++) {
                float2 fh[GNT];
                #pragma unroll
                for (int t = 0; t < GNT; t++)
                    fh[t] = *(const float2*)(my_h + t * HID + 2 * k2);
                #pragma unroll
                for (int kk = 0; kk < 2; kk++) {
                    int k = 2 * k2 + kk;
                    u64 wg = *(const u64*)(s_wg + k * HID + j0);
                    #pragma unroll
                    for (int t = 0; t < GNT; t++)
                        macc[t] = ffma2(dup2(kk ? fh[t].y : fh[t].x), wg, macc[t]);
                }
            }
            #pragma unroll
            for (int t = 0; t < GNT; t++) {
                int node = base + t;
                if (node < N_NODES) {
                    *(float2*)(m    + (size_t)node * HID + j0) = make_float2(lo2(macc[t]), hi2(macc[t]));
                    *(float2*)(aggr + (size_t)node * HID + j0) = make_float2(0.f, 0.f);
                }
            }
        }
        __syncwarp();
    }
}

// =====================================================================
// select + head: out[b] = sigmoid(h[idx[b]] . W_lin + b_lin)
// =====================================================================
__global__ __launch_bounds__(256) void select_kernel(
    const float* __restrict__ h, const int* __restrict__ idx,
    const float* __restrict__ W, const float* __restrict__ bl,
    float* __restrict__ out) {
    int g = blockIdx.x * blockDim.x + threadIdx.x;
    int w = g >> 5, lane = g & 31;
    if (w >= N_IDX) return;
    int node = idx[w];
    const float* hr = h + (size_t)node * HID;
    float s = hr[lane] * W[lane] + hr[32 + lane] * W[32 + lane];
    #pragma unroll
    for (int o = 16; o; o >>= 1) s += __shfl_xor_sync(0xffffffffu, s, o);
    if (lane == 0) out[w] = sigm(s + bl[0]);
}

// =====================================================================
extern "C" void kernel_launch(void* const* d_in, const int* in_sizes, int n_in,
                              void* d_out, int out_size) {
    const float* x        = (const float*)d_in[0];
    const int*   ei       = (const int*)d_in[1];    // int32
    const int*   idx      = (const int*)d_in[2];    // int32
    const float* W_red    = (const float*)d_in[3];
    const float* b_red    = (const float*)d_in[4];
    const float* W_g      = (const float*)d_in[5];
    const float* w_ih     = (const float*)d_in[6];
    const float* w_hh     = (const float*)d_in[7];
    const float* b_ih     = (const float*)d_in[8];
    const float* b_hh     = (const float*)d_in[9];
    const float* W_lin    = (const float*)d_in[10];
    const float* b_lin    = (const float*)d_in[11];
    float* out = (float*)d_out;

    void *ph, *pm, *pa;
    cudaGetSymbolAddress(&ph, g_h);
    cudaGetSymbolAddress(&pm, g_m);
    cudaGetSymbolAddress(&pa, g_aggr);
    float* h_p = (float*)ph;
    float* m_p = (float*)pm;
    float* a_p = (float*)pa;

    const int RED_SMEM = ANNOT * HID * 4 + RNW * RNT * ANNOT * 8;               // ~47 KB
    const int TR_SMEM  = HID * HID * 4 + TNW * TNT * HID * 8;                   // 48 KB
    const int GRU_SMEM = (2 * 192 * HID + HID * HID + 2 * GNW * GNT * HID) * 4; // ~148 KB
    cudaFuncSetAttribute(reduce_kernel,    cudaFuncAttributeMaxDynamicSharedMemorySize, RED_SMEM);
    cudaFuncSetAttribute(transform_kernel, cudaFuncAttributeMaxDynamicSharedMemorySize, TR_SMEM);
    cudaFuncSetAttribute(gru_kernel,       cudaFuncAttributeMaxDynamicSharedMemorySize, GRU_SMEM);

    reduce_kernel<<<592, 512, RED_SMEM>>>(x, W_red, b_red, h_p);
    transform_kernel<<<592, 512, TR_SMEM>>>(h_p, W_g, m_p, a_p);   // m for step 0, aggr = 0
    for (int t = 0; t < N_STEPS; t++) {
        scatter_kernel<<<(N_EDGES * 16) / 256, 256>>>(m_p, ei, a_p);
        int has_next = (t < N_STEPS - 1);
        const float* wg_next = has_next ? (W_g + (size_t)(t + 1) * HID * HID) : W_g;
        gru_kernel<<<148, 384, GRU_SMEM>>>(a_p, h_p, m_p, w_ih, w_hh, b_ih, b_hh, wg_next, has_next);
    }
    select_kernel<<<(N_IDX * 32 + 255) / 256, 256>>>(h_p, idx, W_lin, b_lin, out);
}